// round 12
// baseline (speedup 1.0000x reference)
#include <cuda_runtime.h>
#include <cuda_bf16.h>
#include <cstdint>

#define SEQ 2048
#define HD  64
#define OUT_ELEMS (16*SEQ*HD)

// ---------------- helpers ----------------
__device__ __forceinline__ uint32_t smem_u32(const void* p) {
    uint32_t a;
    asm("{ .reg .u64 t; cvta.to.shared.u64 t, %1; cvt.u32.u64 %0, t; }" : "=r"(a) : "l"(p));
    return a;
}

#define LDSM4(r, a) \
    asm volatile("ldmatrix.sync.aligned.m8n8.x4.shared.b16 {%0,%1,%2,%3}, [%4];" \
        : "=r"((r)[0]), "=r"((r)[1]), "=r"((r)[2]), "=r"((r)[3]) : "r"(a))
#define LDSM2(r, a) \
    asm volatile("ldmatrix.sync.aligned.m8n8.x2.shared.b16 {%0,%1}, [%2];" \
        : "=r"((r)[0]), "=r"((r)[1]) : "r"(a))
#define LDSM2T(r, a) \
    asm volatile("ldmatrix.sync.aligned.m8n8.x2.trans.shared.b16 {%0,%1}, [%2];" \
        : "=r"((r)[0]), "=r"((r)[1]) : "r"(a))

__device__ __forceinline__ void mma16816(float* d, const uint32_t* a, const uint32_t* b) {
    asm volatile(
        "mma.sync.aligned.m16n8k16.row.col.f32.bf16.bf16.f32 "
        "{%0,%1,%2,%3}, {%4,%5,%6,%7}, {%8,%9}, {%0,%1,%2,%3};"
        : "+f"(d[0]), "+f"(d[1]), "+f"(d[2]), "+f"(d[3])
        : "r"(a[0]), "r"(a[1]), "r"(a[2]), "r"(a[3]), "r"(b[0]), "r"(b[1]));
}

// fast 2^t : FFMA-only. |t| < 60 assumed.
__device__ __forceinline__ float fexp2(float t) {
    float z = t + 12582912.0f;
    int   i = __float_as_int(z);
    float f = t - (z - 12582912.0f);
    float p =          1.33335581e-3f;
    p = fmaf(p, f, 9.61812910e-3f);
    p = fmaf(p, f, 5.55041087e-2f);
    p = fmaf(p, f, 2.40226507e-1f);
    p = fmaf(p, f, 6.93147180e-1f);
    p = fmaf(p, f, 1.0f);
    float sc = __int_as_float((i + 127) << 23);
    return p * sc;
}
#define EXSCL 0.18033688011f   // 0.125 * log2(e)

// bf16 tiles: 64 elems (128B) per row, 16B-chunk xor swizzle
#define SW(o) ((o) ^ (((o) >> 3) & 0x70))
__device__ __forceinline__ uint32_t swz(uint32_t base, int row, int chunk) {
    return base + row * 128 + (((chunk ^ (row & 7)) & 7) << 4);
}

// split f32x4 -> bf16 hi/lo, 2x STS.64 (off % 8 == 0 so SW(off+4)==SW(off)+4)
__device__ __forceinline__ void store_split4(float4 v, char* hb, char* lb, int off) {
    __nv_bfloat162 h0 = __floats2bfloat162_rn(v.x, v.y);
    __nv_bfloat162 h1 = __floats2bfloat162_rn(v.z, v.w);
    float2 f0 = __bfloat1622float2(h0), f1 = __bfloat1622float2(h1);
    __nv_bfloat162 l0 = __floats2bfloat162_rn(v.x - f0.x, v.y - f0.y);
    __nv_bfloat162 l1 = __floats2bfloat162_rn(v.z - f1.x, v.w - f1.y);
    int s0 = SW(off);
    uint2 hp = make_uint2(reinterpret_cast<uint32_t&>(h0), reinterpret_cast<uint32_t&>(h1));
    uint2 lp = make_uint2(reinterpret_cast<uint32_t&>(l0), reinterpret_cast<uint32_t&>(l1));
    *(uint2*)(hb + s0) = hp;
    *(uint2*)(lb + s0) = lp;
}

// ---------------- Fused kernel: scores (+E, rowsum) then PV (+norm, O) -------
// smem: QH 8K | QL 8K | stage0 32K | stage1 32K | rs 768B
// phase1 stage: KH = base, KL = base+16K
// phase2 stage: EH = base, EL = +8K, VH = +16K, VL = +24K
#define F_QH 0
#define F_QL 8192
#define F_ST(s) (16384 + (s)*32768)
#define F_RS 81920
#define F_SZ (F_RS + 768)

__global__ void __launch_bounds__(256, 2) attn_k(
    const float* __restrict__ Q, const float* __restrict__ Kg,
    const float* __restrict__ Vg,
    const int* __restrict__ Mk, const float* __restrict__ P,
    float* __restrict__ E, float* __restrict__ O)
{
    extern __shared__ char sm[];
    const uint32_t sb = smem_u32(sm);
    const int t = threadIdx.x, w = t >> 5, lane = t & 31;
    const int bh = blockIdx.y, q0 = blockIdx.x * 64;

    const float* Qb = Q + ((size_t)bh * SEQ + q0) * HD;
    const float* Kb = Kg + (size_t)bh * SEQ * HD;
    const float* Vb = Vg + (size_t)bh * SEQ * HD;
    float* Eb = E + ((size_t)bh * SEQ + q0) * SEQ;

    // ================= Phase 1: S = QK^T, exp epilogue, rowsum =================
    {
        const int mw = w >> 1, nw = w & 1;   // warp tile: rows mw*16, cols nw*64

        // resident Q (64 x 64) split to smem
#pragma unroll
        for (int i = 0; i < 4; i++) {
            int idx = t + i * 256, r = idx >> 4, c = idx & 15;
            store_split4(*(const float4*)(Qb + r * HD + c * 4), sm + F_QH, sm + F_QL, r * 128 + c * 8);
        }

        const int lr = t >> 4, lc = t & 15;
        float4 kr[8];
#pragma unroll
        for (int i = 0; i < 8; i++)
            kr[i] = *(const float4*)(Kb + (size_t)(lr + i * 16) * HD + lc * 4);

        float rs0 = 0.0f, rs1 = 0.0f;
        const int fr = lane >> 2;
        const int fc = 2 * (lane & 3);

        for (int kt = 0; kt < 16; kt++) {
            char* KH = sm + F_ST(kt & 1);
            char* KL = KH + 16384;
#pragma unroll
            for (int i = 0; i < 8; i++)
                store_split4(kr[i], KH, KL, (lr + i * 16) * 128 + lc * 8);
            __syncthreads();
            if (kt < 15) {
                const float* Kt = Kb + (size_t)(kt + 1) * 128 * HD;
#pragma unroll
                for (int i = 0; i < 8; i++)
                    kr[i] = *(const float4*)(Kt + (size_t)(lr + i * 16) * HD + lc * 4);
            }

            float acc[8][4];
#pragma unroll
            for (int ni = 0; ni < 8; ni++)
#pragma unroll
                for (int j = 0; j < 4; j++) acc[ni][j] = 0.0f;

            const uint32_t khs = smem_u32(KH), kls = smem_u32(KL);
#pragma unroll
            for (int kc = 0; kc < 4; kc++) {
                uint32_t ah[4], al[4];
                LDSM4(ah, swz(sb + F_QH, mw * 16 + (lane & 15), kc * 2 + (lane >> 4)));
                LDSM4(al, swz(sb + F_QL, mw * 16 + (lane & 15), kc * 2 + (lane >> 4)));
#pragma unroll
                for (int ni = 0; ni < 8; ni++) {
                    uint32_t bh2[2], bl2[2];
                    const int nb = nw * 64 + ni * 8 + (lane & 7);
                    LDSM2(bh2, swz(khs, nb, kc * 2 + ((lane >> 3) & 1)));
                    LDSM2(bl2, swz(kls, nb, kc * 2 + ((lane >> 3) & 1)));
                    mma16816(acc[ni], ah, bh2);
                    mma16816(acc[ni], ah, bl2);
                    mma16816(acc[ni], al, bh2);
                }
            }

            const size_t gr0 = ((size_t)(bh * SEQ + q0 + mw * 16 + fr)) * SEQ;
            const size_t cb  = (size_t)kt * 128 + nw * 64 + fc;
#pragma unroll
            for (int ni = 0; ni < 8; ni++) {
                size_t g0 = gr0 + cb + ni * 8;
                int2   m0 = *(const int2*)  (Mk + g0);
                float2 p0 = *(const float2*)(P + g0);
                float2 e0;
                e0.x = m0.x ? (p0.x + 1e-12f) * fexp2(acc[ni][0] * EXSCL) : 0.0f;
                e0.y = m0.y ? (p0.y + 1e-12f) * fexp2(acc[ni][1] * EXSCL) : 0.0f;
                *(float2*)(E + g0) = e0;
                rs0 += e0.x + e0.y;
                size_t g1 = g0 + 8 * SEQ;
                int2   m1 = *(const int2*)  (Mk + g1);
                float2 p1 = *(const float2*)(P + g1);
                float2 e1;
                e1.x = m1.x ? (p1.x + 1e-12f) * fexp2(acc[ni][2] * EXSCL) : 0.0f;
                e1.y = m1.y ? (p1.y + 1e-12f) * fexp2(acc[ni][3] * EXSCL) : 0.0f;
                *(float2*)(E + g1) = e1;
                rs1 += e1.x + e1.y;
            }
        }

        rs0 += __shfl_xor_sync(0xffffffffu, rs0, 1);
        rs0 += __shfl_xor_sync(0xffffffffu, rs0, 2);
        rs1 += __shfl_xor_sync(0xffffffffu, rs1, 1);
        rs1 += __shfl_xor_sync(0xffffffffu, rs1, 2);
        float* rss = (float*)(sm + F_RS);
        if ((lane & 3) == 0) {
            rss[nw * 64 + mw * 16 + fr]     = rs0;
            rss[nw * 64 + mw * 16 + fr + 8] = rs1;
        }
        __syncthreads();
        if (t < 64) rss[128 + t] = 1.0f / (rss[t] + rss[64 + t]);
    }

    // ================= Phase 2: normalize E in place + O = p_attn V ============
    {
        const int mw = w >> 1, nw = w & 1;   // warp tile: rows mw*16, cols nw*32
        const int r_ = t >> 4, c_ = t & 15;
        float* sinv = (float*)(sm + F_RS) + 128;

        float4 er[4], vr[4];
#pragma unroll
        for (int i = 0; i < 4; i++) {
            er[i] = *(const float4*)(Eb + (size_t)(r_ + i * 16) * SEQ + c_ * 4);
            vr[i] = *(const float4*)(Vb + (size_t)(r_ + i * 16) * HD + c_ * 4);
        }

        float acc[4][4];
#pragma unroll
        for (int ni = 0; ni < 4; ni++)
#pragma unroll
            for (int j = 0; j < 4; j++) acc[ni][j] = 0.0f;

        __syncthreads();   // sinv visible; stage buffers free

        for (int kt = 0; kt < 32; kt++) {
            char* EH = sm + F_ST(kt & 1);
            char* EL = EH + 8192;
            char* VH = EH + 16384;
            char* VL = EH + 24576;
#pragma unroll
            for (int i = 0; i < 4; i++) {
                const int r = r_ + i * 16;
                const float inv = sinv[r];
                float4 v = er[i];
                v.x *= inv; v.y *= inv; v.z *= inv; v.w *= inv;
                *(float4*)(Eb + (size_t)r * SEQ + kt * 64 + c_ * 4) = v;
                store_split4(v, EH, EL, r * 128 + c_ * 8);
                store_split4(vr[i], VH, VL, r * 128 + c_ * 8);
            }
            __syncthreads();
            if (kt < 31) {
#pragma unroll
                for (int i = 0; i < 4; i++) {
                    er[i] = *(const float4*)(Eb + (size_t)(r_ + i * 16) * SEQ + (kt + 1) * 64 + c_ * 4);
                    vr[i] = *(const float4*)(Vb + (size_t)((kt + 1) * 64 + r_ + i * 16) * HD + c_ * 4);
                }
            }
            const uint32_t ehs = smem_u32(EH), els = smem_u32(EL);
            const uint32_t vhs = smem_u32(VH), vls = smem_u32(VL);
#pragma unroll
            for (int kc = 0; kc < 4; kc++) {
                uint32_t bhf[4][2], blf[4][2];
#pragma unroll
                for (int ni = 0; ni < 4; ni++) {
                    const int nch = nw * 4 + ni;
                    LDSM2T(bhf[ni], swz(vhs, kc * 16 + (lane & 15), nch));
                    LDSM2T(blf[ni], swz(vls, kc * 16 + (lane & 15), nch));
                }
                uint32_t ah[4], al[4];
                LDSM4(ah, swz(ehs, mw * 16 + (lane & 15), kc * 2 + (lane >> 4)));
                LDSM4(al, swz(els, mw * 16 + (lane & 15), kc * 2 + (lane >> 4)));
#pragma unroll
                for (int ni = 0; ni < 4; ni++) {
                    mma16816(acc[ni], ah, bhf[ni]);
                    mma16816(acc[ni], ah, blf[ni]);
                    mma16816(acc[ni], al, bhf[ni]);
                }
            }
        }

        const int r0 = mw * 16 + (lane >> 2);
        const int c0 = nw * 32 + 2 * (lane & 3);
#pragma unroll
        for (int ni = 0; ni < 4; ni++) {
            size_t g0 = ((size_t)(bh * SEQ + q0 + r0)) * HD + c0 + ni * 8;
            *(float2*)(O + g0) = make_float2(acc[ni][0], acc[ni][1]);
            *(float2*)(O + g0 + 8 * HD) = make_float2(acc[ni][2], acc[ni][3]);
        }
    }
}

extern "C" void kernel_launch(void* const* d_in, const int* in_sizes, int n_in,
                              void* d_out, int out_size) {
    const float* Q = (const float*)d_in[0];
    const float* K = (const float*)d_in[1];
    const float* V = (const float*)d_in[2];
    const int*   M = (const int*)  d_in[3];
    const float* P = (const float*)d_in[4];
    float* out = (float*)d_out;
    float* E   = out + OUT_ELEMS;

    cudaFuncSetAttribute(attn_k, cudaFuncAttributeMaxDynamicSharedMemorySize, F_SZ);
    attn_k<<<dim3(32, 16), 256, F_SZ>>>(Q, K, V, M, P, E, out);
}

// round 13
// speedup vs baseline: 1.0274x; 1.0274x over previous
#include <cuda_runtime.h>
#include <cuda_bf16.h>
#include <cstdint>

#define SEQ 2048
#define HD  64
#define OUT_ELEMS (16*SEQ*HD)

__device__ float g_rowsum[16 * SEQ];

// ---------------- helpers ----------------
__device__ __forceinline__ uint32_t smem_u32(const void* p) {
    uint32_t a;
    asm("{ .reg .u64 t; cvta.to.shared.u64 t, %1; cvt.u32.u64 %0, t; }" : "=r"(a) : "l"(p));
    return a;
}

#define LDSM4(r, a) \
    asm volatile("ldmatrix.sync.aligned.m8n8.x4.shared.b16 {%0,%1,%2,%3}, [%4];" \
        : "=r"((r)[0]), "=r"((r)[1]), "=r"((r)[2]), "=r"((r)[3]) : "r"(a))
#define LDSM4T(r, a) \
    asm volatile("ldmatrix.sync.aligned.m8n8.x4.trans.shared.b16 {%0,%1,%2,%3}, [%4];" \
        : "=r"((r)[0]), "=r"((r)[1]), "=r"((r)[2]), "=r"((r)[3]) : "r"(a))

__device__ __forceinline__ void mma16816(float* d, const uint32_t* a, const uint32_t* b) {
    asm volatile(
        "mma.sync.aligned.m16n8k16.row.col.f32.bf16.bf16.f32 "
        "{%0,%1,%2,%3}, {%4,%5,%6,%7}, {%8,%9}, {%0,%1,%2,%3};"
        : "+f"(d[0]), "+f"(d[1]), "+f"(d[2]), "+f"(d[3])
        : "r"(a[0]), "r"(a[1]), "r"(a[2]), "r"(a[3]), "r"(b[0]), "r"(b[1]));
}

// fast 2^t : FFMA-only. |t| < 60 assumed.
__device__ __forceinline__ float fexp2(float t) {
    float z = t + 12582912.0f;
    int   i = __float_as_int(z);
    float f = t - (z - 12582912.0f);
    float p =          1.33335581e-3f;
    p = fmaf(p, f, 9.61812910e-3f);
    p = fmaf(p, f, 5.55041087e-2f);
    p = fmaf(p, f, 2.40226507e-1f);
    p = fmaf(p, f, 6.93147180e-1f);
    p = fmaf(p, f, 1.0f);
    float sc = __int_as_float((i + 127) << 23);
    return p * sc;
}
#define EXSCL 0.18033688011f   // 0.125 * log2(e)

// bf16 tiles: 64 elems (128B) per row, 16B-chunk xor swizzle
#define SW(o) ((o) ^ (((o) >> 3) & 0x70))
__device__ __forceinline__ uint32_t swz(uint32_t base, int row, int chunk) {
    return base + row * 128 + (((chunk ^ (row & 7)) & 7) << 4);
}

// split f32x4 -> bf16 hi/lo, 2x STS.64 (off % 8 == 0 so SW(off+4)==SW(off)+4)
__device__ __forceinline__ void store_split4(float4 v, char* hb, char* lb, int off) {
    __nv_bfloat162 h0 = __floats2bfloat162_rn(v.x, v.y);
    __nv_bfloat162 h1 = __floats2bfloat162_rn(v.z, v.w);
    float2 f0 = __bfloat1622float2(h0), f1 = __bfloat1622float2(h1);
    __nv_bfloat162 l0 = __floats2bfloat162_rn(v.x - f0.x, v.y - f0.y);
    __nv_bfloat162 l1 = __floats2bfloat162_rn(v.z - f1.x, v.w - f1.y);
    int s0 = SW(off);
    uint2 hp = make_uint2(reinterpret_cast<uint32_t&>(h0), reinterpret_cast<uint32_t&>(h1));
    uint2 lp = make_uint2(reinterpret_cast<uint32_t&>(l0), reinterpret_cast<uint32_t&>(l1));
    *(uint2*)(hb + s0) = hp;
    *(uint2*)(lb + s0) = lp;
}

// ------------------- Kernel A: S=QK^T, exp epilogue, rowsum -------------------
// 64-row q-tiles, double-buffered K stages, register prefetch, direct fragment
// epilogue. smem: QH 8K | QL 8K | K stages 2x32K | rs 512B
#define S_QH 0
#define S_QL 8192
#define S_KH(s) (16384 + (s)*32768)
#define S_KL(s) (16384 + (s)*32768 + 16384)
#define S_RS 81920
#define S_SZ (S_RS + 768)

__global__ void __launch_bounds__(256, 2) scores_k(
    const float* __restrict__ Q, const float* __restrict__ Kg,
    const int* __restrict__ Mk, const float* __restrict__ P, float* __restrict__ E)
{
    extern __shared__ char sm[];
    const uint32_t sb = smem_u32(sm);
    const int t = threadIdx.x, w = t >> 5, lane = t & 31;
    const int mw = w >> 1, nw = w & 1;     // warp tile: rows mw*16, cols nw*64
    const int bh = blockIdx.y, q0 = blockIdx.x * 64;

    const float* Qb = Q + ((size_t)bh * SEQ + q0) * HD;
    const float* Kb = Kg + (size_t)bh * SEQ * HD;

    // resident Q (64 x 64) split to smem
#pragma unroll
    for (int i = 0; i < 4; i++) {
        int idx = t + i * 256, r = idx >> 4, c = idx & 15;
        store_split4(*(const float4*)(Qb + r * HD + c * 4), sm + S_QH, sm + S_QL, r * 128 + c * 8);
    }

    // prefetch K tile 0 (128 rows x 64 cols)
    const int lr = t >> 4, lc = t & 15;
    float4 kr[8];
#pragma unroll
    for (int i = 0; i < 8; i++)
        kr[i] = *(const float4*)(Kb + (size_t)(lr + i * 16) * HD + lc * 4);

    float rs0 = 0.0f, rs1 = 0.0f;
    const int fr = lane >> 2;
    const int fc = 2 * (lane & 3);

    for (int kt = 0; kt < 16; kt++) {
        const int s = kt & 1;
#pragma unroll
        for (int i = 0; i < 8; i++)
            store_split4(kr[i], sm + S_KH(s), sm + S_KL(s), (lr + i * 16) * 128 + lc * 8);
        __syncthreads();
        if (kt < 15) {
            const float* Kt = Kb + (size_t)(kt + 1) * 128 * HD;
#pragma unroll
            for (int i = 0; i < 8; i++)
                kr[i] = *(const float4*)(Kt + (size_t)(lr + i * 16) * HD + lc * 4);
        }

        float acc[8][4];
#pragma unroll
        for (int ni = 0; ni < 8; ni++)
#pragma unroll
            for (int j = 0; j < 4; j++) acc[ni][j] = 0.0f;

        // B-fragment x4 addressing: lanes 0-7 -> [n+0..7, k lo], 8-15 -> [n, k hi],
        // 16-23 -> [n+8, k lo], 24-31 -> [n+8, k hi]
        const int brow_off = ((lane >> 4) << 3) + (lane & 7);
        const int bchk_off = (lane >> 3) & 1;
#pragma unroll
        for (int kc = 0; kc < 4; kc++) {
            uint32_t ah[4], al[4];
            LDSM4(ah, swz(sb + S_QH, mw * 16 + (lane & 15), kc * 2 + (lane >> 4)));
            LDSM4(al, swz(sb + S_QL, mw * 16 + (lane & 15), kc * 2 + (lane >> 4)));
#pragma unroll
            for (int ni2 = 0; ni2 < 4; ni2++) {
                uint32_t bh4[4], bl4[4];
                const int nb = nw * 64 + ni2 * 16 + brow_off;
                LDSM4(bh4, swz(sb + S_KH(s), nb, kc * 2 + bchk_off));
                LDSM4(bl4, swz(sb + S_KL(s), nb, kc * 2 + bchk_off));
                mma16816(acc[2 * ni2],     ah, bh4);
                mma16816(acc[2 * ni2],     ah, bl4);
                mma16816(acc[2 * ni2],     al, bh4);
                mma16816(acc[2 * ni2 + 1], ah, bh4 + 2);
                mma16816(acc[2 * ni2 + 1], ah, bl4 + 2);
                mma16816(acc[2 * ni2 + 1], al, bh4 + 2);
            }
        }

        // direct fragment epilogue: e = mask ? (p+1e-12)*2^(s*c) : 0
        const size_t gr0 = ((size_t)(bh * SEQ + q0 + mw * 16 + fr)) * SEQ;
        const size_t cb  = (size_t)kt * 128 + nw * 64 + fc;
#pragma unroll
        for (int ni = 0; ni < 8; ni++) {
            size_t g0 = gr0 + cb + ni * 8;
            int2   m0 = *(const int2*)  (Mk + g0);
            float2 p0 = *(const float2*)(P + g0);
            float2 e0;
            e0.x = m0.x ? (p0.x + 1e-12f) * fexp2(acc[ni][0] * EXSCL) : 0.0f;
            e0.y = m0.y ? (p0.y + 1e-12f) * fexp2(acc[ni][1] * EXSCL) : 0.0f;
            *(float2*)(E + g0) = e0;
            rs0 += e0.x + e0.y;
            size_t g1 = g0 + 8 * SEQ;
            int2   m1 = *(const int2*)  (Mk + g1);
            float2 p1 = *(const float2*)(P + g1);
            float2 e1;
            e1.x = m1.x ? (p1.x + 1e-12f) * fexp2(acc[ni][2] * EXSCL) : 0.0f;
            e1.y = m1.y ? (p1.y + 1e-12f) * fexp2(acc[ni][3] * EXSCL) : 0.0f;
            *(float2*)(E + g1) = e1;
            rs1 += e1.x + e1.y;
        }
    }

    rs0 += __shfl_xor_sync(0xffffffffu, rs0, 1);
    rs0 += __shfl_xor_sync(0xffffffffu, rs0, 2);
    rs1 += __shfl_xor_sync(0xffffffffu, rs1, 1);
    rs1 += __shfl_xor_sync(0xffffffffu, rs1, 2);
    float* rss = (float*)(sm + S_RS);
    if ((lane & 3) == 0) {
        rss[nw * 64 + mw * 16 + fr]     = rs0;
        rss[nw * 64 + mw * 16 + fr + 8] = rs1;
    }
    __syncthreads();
    if (t < 64) g_rowsum[bh * SEQ + q0 + t] = rss[t] + rss[64 + t];
}

// --------------- Kernel B: normalize E in place + O = p_attn V ---------------
#define B_EH(s) ((s)*32768)
#define B_EL(s) ((s)*32768 + 8192)
#define B_VH(s) ((s)*32768 + 16384)
#define B_VL(s) ((s)*32768 + 24576)
#define B_IV 65536
#define B_SZ (B_IV + 256)

__global__ void __launch_bounds__(256, 2) pv_k(
    const float* __restrict__ Vg, float* __restrict__ E, float* __restrict__ O)
{
    extern __shared__ char sm[];
    const uint32_t sb = smem_u32(sm);
    const int t = threadIdx.x, w = t >> 5, lane = t & 31;
    const int mw = w >> 1, nw = w & 1;
    const int bh = blockIdx.y, q0 = blockIdx.x * 64;

    float* sinv = (float*)(sm + B_IV);
    if (t < 64) sinv[t] = 1.0f / g_rowsum[bh * SEQ + q0 + t];

    float* Eb = E + ((size_t)bh * SEQ + q0) * SEQ;
    const float* Vb = Vg + (size_t)bh * SEQ * HD;

    const int r_ = t >> 4, c_ = t & 15;

    float4 er[4], vr[4];
#pragma unroll
    for (int i = 0; i < 4; i++) {
        er[i] = *(const float4*)(Eb + (size_t)(r_ + i * 16) * SEQ + c_ * 4);
        vr[i] = *(const float4*)(Vb + (size_t)(r_ + i * 16) * HD + c_ * 4);
    }

    float acc[4][4];
#pragma unroll
    for (int ni = 0; ni < 4; ni++)
#pragma unroll
        for (int j = 0; j < 4; j++) acc[ni][j] = 0.0f;

    __syncthreads();

    for (int kt = 0; kt < 32; kt++) {
        const int s = kt & 1;
#pragma unroll
        for (int i = 0; i < 4; i++) {
            const int r = r_ + i * 16;
            const float inv = sinv[r];
            float4 v = er[i];
            v.x *= inv; v.y *= inv; v.z *= inv; v.w *= inv;
            *(float4*)(Eb + (size_t)r * SEQ + kt * 64 + c_ * 4) = v;
            store_split4(v, sm + B_EH(s), sm + B_EL(s), r * 128 + c_ * 8);
            store_split4(vr[i], sm + B_VH(s), sm + B_VL(s), r * 128 + c_ * 8);
        }
        __syncthreads();
        if (kt < 31) {
#pragma unroll
            for (int i = 0; i < 4; i++) {
                er[i] = *(const float4*)(Eb + (size_t)(r_ + i * 16) * SEQ + (kt + 1) * 64 + c_ * 4);
                vr[i] = *(const float4*)(Vb + (size_t)((kt + 1) * 64 + r_ + i * 16) * HD + c_ * 4);
            }
        }
        // V fragments via x4.trans: lanes 0-15 -> chunk c, k rows 0-15;
        // lanes 16-31 -> chunk c+1. r = {c:k0, c:k1, c+1:k0, c+1:k1}
        const int vchk_off = lane >> 4;
#pragma unroll
        for (int kc = 0; kc < 4; kc++) {
            uint32_t bhf[2][4], blf[2][4];
#pragma unroll
            for (int ni2 = 0; ni2 < 2; ni2++) {
                const int nch = nw * 4 + ni2 * 2 + vchk_off;
                LDSM4T(bhf[ni2], swz(sb + B_VH(s), kc * 16 + (lane & 15), nch));
                LDSM4T(blf[ni2], swz(sb + B_VL(s), kc * 16 + (lane & 15), nch));
            }
            uint32_t ah[4], al[4];
            LDSM4(ah, swz(sb + B_EH(s), mw * 16 + (lane & 15), kc * 2 + (lane >> 4)));
            LDSM4(al, swz(sb + B_EL(s), mw * 16 + (lane & 15), kc * 2 + (lane >> 4)));
#pragma unroll
            for (int ni2 = 0; ni2 < 2; ni2++) {
                mma16816(acc[2 * ni2],     ah, bhf[ni2]);
                mma16816(acc[2 * ni2],     ah, blf[ni2]);
                mma16816(acc[2 * ni2],     al, bhf[ni2]);
                mma16816(acc[2 * ni2 + 1], ah, bhf[ni2] + 2);
                mma16816(acc[2 * ni2 + 1], ah, blf[ni2] + 2);
                mma16816(acc[2 * ni2 + 1], al, bhf[ni2] + 2);
            }
        }
    }

    const int r0 = mw * 16 + (lane >> 2);
    const int c0 = nw * 32 + 2 * (lane & 3);
#pragma unroll
    for (int ni = 0; ni < 4; ni++) {
        size_t g0 = ((size_t)(bh * SEQ + q0 + r0)) * HD + c0 + ni * 8;
        *(float2*)(O + g0) = make_float2(acc[ni][0], acc[ni][1]);
        *(float2*)(O + g0 + 8 * HD) = make_float2(acc[ni][2], acc[ni][3]);
    }
}

extern "C" void kernel_launch(void* const* d_in, const int* in_sizes, int n_in,
                              void* d_out, int out_size) {
    const float* Q = (const float*)d_in[0];
    const float* K = (const float*)d_in[1];
    const float* V = (const float*)d_in[2];
    const int*   M = (const int*)  d_in[3];
    const float* P = (const float*)d_in[4];
    float* out = (float*)d_out;
    float* E   = out + OUT_ELEMS;

    cudaFuncSetAttribute(scores_k, cudaFuncAttributeMaxDynamicSharedMemorySize, S_SZ);
    cudaFuncSetAttribute(pv_k,     cudaFuncAttributeMaxDynamicSharedMemorySize, B_SZ);

    scores_k<<<dim3(32, 16), 256, S_SZ>>>(Q, K, M, P, E);
    pv_k<<<dim3(32, 16), 256, B_SZ>>>(V, E, out);
}